// round 5
// baseline (speedup 1.0000x reference)
#include <cuda_runtime.h>
#include <math.h>

typedef unsigned long long ull;

// ---------------- problem constants ----------------
constexpr int CH   = 120;
constexpr int NWIN = 1024;          // total windows (4 * 4 * 8 * 8)
constexpr int NTOK = NWIN * 128;    // 131072
constexpr float SCALE_F = 0.22360679774997896f;  // 20^-0.5

// ---------------- scratch ----------------
__device__ float g_xw   [(size_t)NTOK * CH];    // LN1'd, rolled, windowed
__device__ float g_qkv_s[(size_t)NTOK * 360];   // layout [win][360][128]
__device__ float g_qkv_m[(size_t)NTOK * 360];   // layout [win][360][128]
__device__ float g_xout [(size_t)NTOK * 240];   // layout [win][240][128]
__device__ float g_xres [(size_t)NTOK * CH];    // x + attn branch (plain layout)
__device__ float g_z    [(size_t)NTOK * CH];    // LN2 output
__device__ float g_h    [(size_t)NTOK * 480];   // fc11|fc12 pre-activations

// ---------------- f32x2 helpers (attention only) ----------------
__device__ __forceinline__ void fma2(ull& d, ull a, ull b) {
    asm("fma.rn.f32x2 %0, %1, %2, %0;" : "+l"(d) : "l"(a), "l"(b));
}
__device__ __forceinline__ ull pack2(float lo, float hi) {
    ull r; asm("mov.b64 %0, {%1, %2};" : "=l"(r) : "f"(lo), "f"(hi)); return r;
}
__device__ __forceinline__ float2 u2f(ull v) {
    float2 f; asm("mov.b64 {%0, %1}, %2;" : "=f"(f.x), "=f"(f.y) : "l"(v)); return f;
}

__device__ __forceinline__ float gelu_exact(float v) {
    return 0.5f * v * (1.0f + erff(v * 0.70710678118654752f));
}

// token (wi,t) -> rolled source/dest offset in (B,D,H,W,C) layout
__device__ __forceinline__ size_t roll_offset(int wi, int t) {
    int wB = wi & 7, hB = (wi >> 3) & 7, dB = (wi >> 6) & 3, bb = wi >> 8;
    int dt = t >> 6, ht = (t >> 3) & 7, wt = t & 7;
    int ds = (dB * 2 + dt + 1) & 7;
    int hs = (hB * 8 + ht + 4) & 63;
    int ws = (wB * 8 + wt + 4) & 63;
    return (size_t)((((bb * 8 + ds) * 64 + hs) * 64 + ws)) * CH;
}

// ---------------- K1: LN1 + roll + window partition ----------------
__global__ void k_ln1(const float* __restrict__ x, const float* __restrict__ g,
                      const float* __restrict__ b) {
    int warp = (blockIdx.x * blockDim.x + threadIdx.x) >> 5;
    int lane = threadIdx.x & 31;
    if (warp >= NTOK) return;
    int wi = warp >> 7, t = warp & 127;
    const float* src = x + roll_offset(wi, t);
    float v0 = 0, v1 = 0, v2 = 0, v3 = 0, s = 0, sq = 0;
    if (lane < 30) {
        float4 f = *(const float4*)(src + lane * 4);
        v0 = f.x; v1 = f.y; v2 = f.z; v3 = f.w;
        s  = v0 + v1 + v2 + v3;
        sq = v0 * v0 + v1 * v1 + v2 * v2 + v3 * v3;
    }
#pragma unroll
    for (int o = 16; o; o >>= 1) {
        s  += __shfl_xor_sync(0xffffffffu, s, o);
        sq += __shfl_xor_sync(0xffffffffu, sq, o);
    }
    float mean = s * (1.0f / 120.0f);
    float var  = sq * (1.0f / 120.0f) - mean * mean;
    float r = rsqrtf(var + 1e-5f);
    if (lane < 30) {
        int c = lane * 4;
        float* dst = g_xw + (size_t)warp * CH + c;
        dst[0] = (v0 - mean) * r * g[c]     + b[c];
        dst[1] = (v1 - mean) * r * g[c + 1] + b[c + 1];
        dst[2] = (v2 - mean) * r * g[c + 2] + b[c + 2];
        dst[3] = (v3 - mean) * r * g[c + 3] + b[c + 3];
    }
}

// ---------------- LN2 (plain layout) ----------------
__global__ void k_ln2(const float* __restrict__ g, const float* __restrict__ b) {
    int warp = (blockIdx.x * blockDim.x + threadIdx.x) >> 5;
    int lane = threadIdx.x & 31;
    if (warp >= NTOK) return;
    const float* src = g_xres + (size_t)warp * CH;
    float v0 = 0, v1 = 0, v2 = 0, v3 = 0, s = 0, sq = 0;
    if (lane < 30) {
        float4 f = *(const float4*)(src + lane * 4);
        v0 = f.x; v1 = f.y; v2 = f.z; v3 = f.w;
        s  = v0 + v1 + v2 + v3;
        sq = v0 * v0 + v1 * v1 + v2 * v2 + v3 * v3;
    }
#pragma unroll
    for (int o = 16; o; o >>= 1) {
        s  += __shfl_xor_sync(0xffffffffu, s, o);
        sq += __shfl_xor_sync(0xffffffffu, sq, o);
    }
    float mean = s * (1.0f / 120.0f);
    float var  = sq * (1.0f / 120.0f) - mean * mean;
    float r = rsqrtf(var + 1e-5f);
    if (lane < 30) {
        int c = lane * 4;
        float* dst = g_z + (size_t)warp * CH + c;
        dst[0] = (v0 - mean) * r * g[c]     + b[c];
        dst[1] = (v1 - mean) * r * g[c + 1] + b[c + 1];
        dst[2] = (v2 - mean) * r * g[c + 2] + b[c + 2];
        dst[3] = (v3 - mean) * r * g[c + 3] + b[c + 3];
    }
}

// ---------------- generic SGEMM: out = A @ B^T + epilogue ----------------
// MODE 0: qkv self (A=g_xw, K=120, N=360, out [win][n][128] via smem transpose)
// MODE 1: qkv mut  (A=g_xw + pos(extra), rest same as MODE 0)
// MODE 2: proj     (A=g_xout [win][240][128], K=240, N=120,
//                   epi: scatter(roll) + x(extra) add -> g_xres row-major)
// MODE 3: mlp1     (B split fc11/fc12, K=120, N=480, out row-major)
// MODE 4: mlp2     (A = gelu-gate from g_h (phys 480), K=240, N=120,
//                   epi: + g_xres(extra) -> d_out row-major)
template <int KD, int MODE>
__global__ void __launch_bounds__(256) k_gemm(
    const float* __restrict__ A, const float* __restrict__ B1,
    const float* __restrict__ B2, const float* __restrict__ bias,
    const float* __restrict__ bias2, const float* __restrict__ extra,
    float* __restrict__ out, int Ntot) {
    __shared__ float smem_all[2048];
    float* As = smem_all;          // [8][128]
    float* Bs = smem_all + 1024;   // [8][128]
    int tid = threadIdx.x;
    int m0 = blockIdx.x * 128;
    int n0 = blockIdx.y * 128;
    int tx = tid & 15, ty = tid >> 4;
    int lr = tid >> 1;          // load row 0..127
    int lc = (tid & 1) * 4;     // load col offset (0 or 4)
    int win = m0 >> 7;

    float acc[2][4][2][4];      // [gi][i][gj][j]
#pragma unroll
    for (int a = 0; a < 2; a++)
#pragma unroll
        for (int i = 0; i < 4; i++)
#pragma unroll
            for (int g = 0; g < 2; g++)
#pragma unroll
                for (int j = 0; j < 4; j++) acc[a][i][g][j] = 0.0f;

    int am = m0 + lr;
    int bn = n0 + lr;
    bool bvalid = bn < Ntot;
    const float* bsrc;
    if (MODE == 3) {
        bsrc = (bn < 240) ? (B1 + (size_t)bn * KD)
                          : (B2 + (size_t)(bn - 240) * KD);
    } else {
        bsrc = B1 + (size_t)(bvalid ? bn : 0) * KD;
    }

    // ---- load helper ----
    auto load_tile = [&](int k0, float4& av, float4& bv) {
        if (MODE == 2) {
            int kk = tid >> 5;
            int mc = (tid & 31) * 4;
            av = *(const float4*)(A + ((size_t)win * 240 + k0 + kk) * 128 + mc);
        } else if (MODE == 4) {
            const float* hp = A + (size_t)am * 480 + k0 + lc;
            float4 h1 = *(const float4*)hp;
            float4 h2 = *(const float4*)(hp + 240);
            av.x = gelu_exact(h1.x) * h2.x;
            av.y = gelu_exact(h1.y) * h2.y;
            av.z = gelu_exact(h1.z) * h2.z;
            av.w = gelu_exact(h1.w) * h2.w;
        } else {
            av = *(const float4*)(A + (size_t)am * KD + k0 + lc);
            if (MODE == 1) {
                int tt = am & 63;
                float4 p = *(const float4*)(extra + (size_t)tt * CH + k0 + lc);
                av.x += p.x; av.y += p.y; av.z += p.z; av.w += p.w;
            }
        }
        bv = make_float4(0.f, 0.f, 0.f, 0.f);
        if (bvalid) bv = *(const float4*)(bsrc + k0 + lc);
    };

    float4 av, bv;
    load_tile(0, av, bv);

    for (int k0 = 0; k0 < KD; k0 += 8) {
        __syncthreads();
        if (MODE == 2) {
            int kk = tid >> 5;
            int mc = (tid & 31) * 4;
            *(float4*)&As[kk * 128 + mc] = av;
        } else {
            As[(lc + 0) * 128 + lr] = av.x; As[(lc + 1) * 128 + lr] = av.y;
            As[(lc + 2) * 128 + lr] = av.z; As[(lc + 3) * 128 + lr] = av.w;
        }
        Bs[(lc + 0) * 128 + lr] = bv.x; Bs[(lc + 1) * 128 + lr] = bv.y;
        Bs[(lc + 2) * 128 + lr] = bv.z; Bs[(lc + 3) * 128 + lr] = bv.w;
        __syncthreads();
        if (k0 + 8 < KD) load_tile(k0 + 8, av, bv);

#pragma unroll
        for (int kk = 0; kk < 8; kk++) {
            float a0[4], a1[4], b0[4], b1[4];
            *(float4*)a0 = *(const float4*)&As[kk * 128 + ty * 4];
            *(float4*)a1 = *(const float4*)&As[kk * 128 + 64 + ty * 4];
            *(float4*)b0 = *(const float4*)&Bs[kk * 128 + tx * 4];
            *(float4*)b1 = *(const float4*)&Bs[kk * 128 + 64 + tx * 4];
#pragma unroll
            for (int i = 0; i < 4; i++)
#pragma unroll
                for (int j = 0; j < 4; j++) {
                    acc[0][i][0][j] += a0[i] * b0[j];
                    acc[0][i][1][j] += a0[i] * b1[j];
                    acc[1][i][0][j] += a1[i] * b0[j];
                    acc[1][i][1][j] += a1[i] * b1[j];
                }
        }
    }

    if (MODE == 0 || MODE == 1) {
        // transposed coalesced epilogue: write [n][128] tile of window `win`
        __syncthreads();
        int nrow = tid >> 4;            // 0..15
        int mcol = (tid & 15) * 8;
#pragma unroll 1
        for (int c = 0; c < 8; c++) {
            int gj = c >> 2;
            if ((tx >> 2) == (c & 3)) {
#pragma unroll
                for (int j = 0; j < 4; j++) {
                    int nr = (tx & 3) * 4 + j;
#pragma unroll
                    for (int gi = 0; gi < 2; gi++)
#pragma unroll
                        for (int i = 0; i < 4; i++)
                            smem_all[nr * 128 + gi * 64 + ty * 4 + i] =
                                acc[gi][i][gj][j];
                }
            }
            __syncthreads();
            int n = n0 + c * 16 + nrow;
            if (n < Ntot) {
                float bz = bias[n];
                float4 x1 = *(float4*)&smem_all[nrow * 128 + mcol];
                float4 x2 = *(float4*)&smem_all[nrow * 128 + mcol + 4];
                x1.x += bz; x1.y += bz; x1.z += bz; x1.w += bz;
                x2.x += bz; x2.y += bz; x2.z += bz; x2.w += bz;
                float* op = out + ((size_t)win * 360 + n) * 128 + mcol;
                *(float4*)op = x1;
                *(float4*)(op + 4) = x2;
            }
            __syncthreads();
        }
        return;
    }

    // vectorized epilogues (MODE 2/3/4): j-quads contiguous & 16B-aligned
#pragma unroll
    for (int gi = 0; gi < 2; gi++)
#pragma unroll
        for (int i = 0; i < 4; i++) {
            int m = m0 + gi * 64 + ty * 4 + i;
            size_t drow;
            if (MODE == 2) {
                drow = roll_offset(m >> 7, m & 127);
            } else {
                drow = (size_t)m * Ntot;
            }
#pragma unroll
            for (int gj = 0; gj < 2; gj++) {
                int n = n0 + gj * 64 + tx * 4;
                if (n >= Ntot) continue;
                float4 v = make_float4(acc[gi][i][gj][0], acc[gi][i][gj][1],
                                       acc[gi][i][gj][2], acc[gi][i][gj][3]);
                if (MODE == 2) {
                    float4 e = *(const float4*)(extra + drow + n);
                    float4 bz = *(const float4*)(bias + n);
                    v.x += bz.x + e.x; v.y += bz.y + e.y;
                    v.z += bz.z + e.z; v.w += bz.w + e.w;
                } else if (MODE == 3) {
                    const float* bp = (n < 240) ? (bias + n) : (bias2 + n - 240);
                    float4 bz = *(const float4*)bp;
                    v.x += bz.x; v.y += bz.y; v.z += bz.z; v.w += bz.w;
                } else {  // MODE 4
                    float4 e = *(const float4*)(extra + (size_t)m * 120 + n);
                    float4 bz = *(const float4*)(bias + n);
                    v.x += bz.x + e.x; v.y += bz.y + e.y;
                    v.z += bz.z + e.z; v.w += bz.w + e.w;
                }
                *(float4*)(out + drow + n) = v;
            }
        }
}

// ---------------- K4: attention (self + mutual), block = (window, head) ----
__global__ void __launch_bounds__(128) k_attn(const float* __restrict__ rpb) {
    __shared__ float sk[128 * 24];
    __shared__ float sv[128 * 24];
    __shared__ float srpb[675];
    __shared__ int   sg[128];

    int wi = blockIdx.x, h = blockIdx.y;
    int t = threadIdx.x;

    for (int i = t; i < 675; i += 128) srpb[i] = rpb[i * 6 + h];

    // token / window coordinates
    int dt = t >> 6, ht = (t >> 3) & 7, wt = t & 7;
    int dB = (wi >> 6) & 3, hB = (wi >> 3) & 7, wB = wi & 7;
    int dd = dB * 2 + dt, hh = hB * 8 + ht, ww = wB * 8 + wt;
    int gd = (dd < 6) ? 0 : ((dd < 7) ? 1 : 2);
    int gh = (hh < 56) ? 0 : ((hh < 60) ? 1 : 2);
    int gw = (ww < 56) ? 0 : ((ww < 60) ? 1 : 2);
    int grp = gd * 9 + gh * 3 + gw;
    int gd0 = (dB * 2 < 6) ? 0 : 1;
    int grp0 = gd0 * 9 + gh * 3 + gw;
    int ccode = dt * 225 + ht * 15 + wt;
    sg[t] = ccode | (grp << 10) | (grp0 << 16);
    int rbase = (dt + 1) * 225 + (ht + 7) * 15 + (wt + 7);

    // ---- self QKV load (coalesced) ----
    const float* Q = g_qkv_s + (size_t)wi * 360 * 128;
    ull q2[10];
#pragma unroll
    for (int d = 0; d < 10; d++) {
        float lo = Q[(h * 20 + 2 * d) * 128 + t] * SCALE_F;
        float hi = Q[(h * 20 + 2 * d + 1) * 128 + t] * SCALE_F;
        q2[d] = pack2(lo, hi);
    }
#pragma unroll
    for (int d = 0; d < 20; d++) {
        sk[t * 24 + d] = Q[(120 + h * 20 + d) * 128 + t];
        sv[t * 24 + d] = Q[(240 + h * 20 + d) * 128 + t];
    }
    __syncthreads();

    ull o2[10];
#pragma unroll
    for (int d = 0; d < 10; d++) o2[d] = 0ULL;
    float sum = 0.f;

#pragma unroll 2
    for (int m = 0; m < 128; m++) {
        int s = sg[m];
        const ulonglong2* kr = (const ulonglong2*)(sk + m * 24);
        ulonglong2 k0 = kr[0], k1 = kr[1], k2 = kr[2], k3 = kr[3], k4 = kr[4];
        ull aA = 0ULL, aB = 0ULL;
        fma2(aA, q2[0], k0.x); fma2(aB, q2[1], k0.y);
        fma2(aA, q2[2], k1.x); fma2(aB, q2[3], k1.y);
        fma2(aA, q2[4], k2.x); fma2(aB, q2[5], k2.y);
        fma2(aA, q2[6], k3.x); fma2(aB, q2[7], k3.y);
        fma2(aA, q2[8], k4.x); fma2(aB, q2[9], k4.y);
        float2 fa = u2f(aA), fb = u2f(aB);
        float logit = (fa.x + fa.y) + (fb.x + fb.y) + srpb[rbase - (s & 1023)];
        float p = (((s >> 10) & 31) == grp) ? __expf(logit) : 0.f;
        sum += p;
        ull pd = pack2(p, p);
        const ulonglong2* vr = (const ulonglong2*)(sv + m * 24);
        ulonglong2 v0 = vr[0], v1 = vr[1], v2 = vr[2], v3 = vr[3], v4 = vr[4];
        fma2(o2[0], pd, v0.x); fma2(o2[1], pd, v0.y);
        fma2(o2[2], pd, v1.x); fma2(o2[3], pd, v1.y);
        fma2(o2[4], pd, v2.x); fma2(o2[5], pd, v2.y);
        fma2(o2[6], pd, v3.x); fma2(o2[7], pd, v3.y);
        fma2(o2[8], pd, v4.x); fma2(o2[9], pd, v4.y);
    }
    {
        float inv = 1.0f / sum;
        float* ob = g_xout + ((size_t)wi * 240 + 120 + h * 20) * 128 + t;
#pragma unroll
        for (int d = 0; d < 10; d++) {
            float2 f = u2f(o2[d]);
            ob[(2 * d) * 128]     = f.x * inv;
            ob[(2 * d + 1) * 128] = f.y * inv;
        }
    }
    __syncthreads();  // done with sk/sv before overwrite

    // ---- mutual attention ----
    int qrow = t ^ 64;
    int mb   = (t < 64) ? 0 : 64;
    const float* Qm = g_qkv_m + (size_t)wi * 360 * 128;
#pragma unroll
    for (int d = 0; d < 20; d++) {
        sk[t * 24 + d] = Qm[(120 + h * 20 + d) * 128 + t];
        sv[t * 24 + d] = Qm[(240 + h * 20 + d) * 128 + t];
    }
#pragma unroll
    for (int d = 0; d < 10; d++) {
        float lo = Qm[(h * 20 + 2 * d) * 128 + qrow] * SCALE_F;
        float hi = Qm[(h * 20 + 2 * d + 1) * 128 + qrow] * SCALE_F;
        q2[d] = pack2(lo, hi);
    }
    __syncthreads();

#pragma unroll
    for (int d = 0; d < 10; d++) o2[d] = 0ULL;
    sum = 0.f;
    int mygrp0 = (sg[t & 63] >> 16) & 31;

#pragma unroll 2
    for (int m = 0; m < 64; m++) {
        int s = sg[m];
        const ulonglong2* kr = (const ulonglong2*)(sk + (mb + m) * 24);
        ulonglong2 k0 = kr[0], k1 = kr[1], k2 = kr[2], k3 = kr[3], k4 = kr[4];
        ull aA = 0ULL, aB = 0ULL;
        fma2(aA, q2[0], k0.x); fma2(aB, q2[1], k0.y);
        fma2(aA, q2[2], k1.x); fma2(aB, q2[3], k1.y);
        fma2(aA, q2[4], k2.x); fma2(aB, q2[5], k2.y);
        fma2(aA, q2[6], k3.x); fma2(aB, q2[7], k3.y);
        fma2(aA, q2[8], k4.x); fma2(aB, q2[9], k4.y);
        float2 fa = u2f(aA), fb = u2f(aB);
        float logit = (fa.x + fa.y) + (fb.x + fb.y);
        float p = (((s >> 16) & 31) == mygrp0) ? __expf(logit) : 0.f;
        sum += p;
        ull pd = pack2(p, p);
        const ulonglong2* vr = (const ulonglong2*)(sv + (mb + m) * 24);
        ulonglong2 v0 = vr[0], v1 = vr[1], v2 = vr[2], v3 = vr[3], v4 = vr[4];
        fma2(o2[0], pd, v0.x); fma2(o2[1], pd, v0.y);
        fma2(o2[2], pd, v1.x); fma2(o2[3], pd, v1.y);
        fma2(o2[4], pd, v2.x); fma2(o2[5], pd, v2.y);
        fma2(o2[6], pd, v3.x); fma2(o2[7], pd, v3.y);
        fma2(o2[8], pd, v4.x); fma2(o2[9], pd, v4.y);
    }
    {
        float inv = 1.0f / sum;
        float* ob = g_xout + ((size_t)wi * 240 + h * 20) * 128 + t;
#pragma unroll
        for (int d = 0; d < 10; d++) {
            float2 f = u2f(o2[d]);
            ob[(2 * d) * 128]     = f.x * inv;
            ob[(2 * d + 1) * 128] = f.y * inv;
        }
    }
}

// ---------------- launch ----------------
extern "C" void kernel_launch(void* const* d_in, const int* in_sizes, int n_in,
                              void* d_out, int out_size) {
    const float* x          = (const float*)d_in[0];
    const float* g1         = (const float*)d_in[2];
    const float* b1         = (const float*)d_in[3];
    const float* qkv_self_w = (const float*)d_in[4];
    const float* qkv_self_b = (const float*)d_in[5];
    const float* qkv_mut_w  = (const float*)d_in[6];
    const float* qkv_mut_b  = (const float*)d_in[7];
    const float* proj_w     = (const float*)d_in[8];
    const float* proj_b     = (const float*)d_in[9];
    const float* rpb        = (const float*)d_in[10];
    const float* pos        = (const float*)d_in[11];
    const float* g2         = (const float*)d_in[12];
    const float* b2         = (const float*)d_in[13];
    const float* fc11_w     = (const float*)d_in[14];
    const float* fc11_b     = (const float*)d_in[15];
    const float* fc12_w     = (const float*)d_in[16];
    const float* fc12_b     = (const float*)d_in[17];
    const float* fc2_w      = (const float*)d_in[18];
    const float* fc2_b      = (const float*)d_in[19];
    float* out = (float*)d_out;

    float* xw   = nullptr; cudaGetSymbolAddress((void**)&xw,   g_xw);
    float* qkvs = nullptr; cudaGetSymbolAddress((void**)&qkvs, g_qkv_s);
    float* qkvm = nullptr; cudaGetSymbolAddress((void**)&qkvm, g_qkv_m);
    float* xo   = nullptr; cudaGetSymbolAddress((void**)&xo,   g_xout);
    float* xres = nullptr; cudaGetSymbolAddress((void**)&xres, g_xres);
    float* zb   = nullptr; cudaGetSymbolAddress((void**)&zb,   g_z);
    float* hb   = nullptr; cudaGetSymbolAddress((void**)&hb,   g_h);

    // 1. LN1 + roll + window partition
    k_ln1<<<NTOK / 8, 256>>>(x, g1, b1);
    // 2. QKV self (-> [win][360][128])
    k_gemm<120, 0><<<dim3(NTOK / 128, 3), 256>>>(
        xw, qkv_self_w, nullptr, qkv_self_b, nullptr, nullptr, qkvs, 360);
    // 3. QKV mutual (+ pos bias on A, -> [win][360][128])
    k_gemm<120, 1><<<dim3(NTOK / 128, 3), 256>>>(
        xw, qkv_mut_w, nullptr, qkv_mut_b, nullptr, pos, qkvm, 360);
    // 4. attention (-> g_xout [win][240][128])
    k_attn<<<dim3(NWIN, 6), 128>>>(rpb);
    // 5. proj + window-reverse + roll-back + shortcut add
    k_gemm<240, 2><<<dim3(NTOK / 128, 1), 256>>>(
        xo, proj_w, nullptr, proj_b, nullptr, x, xres, 120);
    // 6. LN2
    k_ln2<<<NTOK / 8, 256>>>(g2, b2);
    // 7. fc11 | fc12
    k_gemm<120, 3><<<dim3(NTOK / 128, 4), 256>>>(
        zb, fc11_w, fc12_w, fc11_b, fc12_b, nullptr, hb, 480);
    // 8. gelu-gate + fc2 + residual -> out
    k_gemm<240, 4><<<dim3(NTOK / 128, 1), 256>>>(
        hb, fc2_w, nullptr, fc2_b, nullptr, xres, out, 120);
}

// round 9
// speedup vs baseline: 1.6946x; 1.6946x over previous
#include <cuda_runtime.h>
#include <math.h>
#include <stdint.h>

typedef unsigned long long ull;

// ---------------- problem constants ----------------
constexpr int CH   = 120;
constexpr int NWIN = 1024;          // total windows (4 * 4 * 8 * 8)
constexpr int NTOK = NWIN * 128;    // 131072
constexpr float SCALE_F = 0.22360679774997896f;  // 20^-0.5

// ---------------- scratch ----------------
__device__ float g_xw   [(size_t)NTOK * CH];    // LN1'd, rolled, windowed
__device__ float g_qkv_s[(size_t)NTOK * 360];   // layout [win][360][128]
__device__ float g_qkv_m[(size_t)NTOK * 360];   // layout [win][360][128]
__device__ float g_xout [(size_t)NTOK * 240];   // layout [win][240][128]
__device__ float g_xres [(size_t)NTOK * CH];    // x + attn branch (plain layout)
__device__ float g_z    [(size_t)NTOK * CH];    // LN2 output
__device__ float g_h    [(size_t)NTOK * 480];   // fc11|fc12 pre-activations

// ---------------- helpers ----------------
__device__ __forceinline__ void fma2(ull& d, ull a, ull b) {
    asm("fma.rn.f32x2 %0, %1, %2, %0;" : "+l"(d) : "l"(a), "l"(b));
}
__device__ __forceinline__ ull pack2(float lo, float hi) {
    ull r; asm("mov.b64 %0, {%1, %2};" : "=l"(r) : "f"(lo), "f"(hi)); return r;
}
__device__ __forceinline__ float2 u2f(ull v) {
    float2 f; asm("mov.b64 {%0, %1}, %2;" : "=f"(f.x), "=f"(f.y) : "l"(v)); return f;
}
__device__ __forceinline__ float f2tf32(float f) {
    uint32_t r; asm("cvt.rna.tf32.f32 %0, %1;" : "=r"(r) : "f"(f));
    return __uint_as_float(r);
}
__device__ __forceinline__ void mma_tf32(float* d, const uint32_t* a,
                                         const uint32_t* b) {
    asm("mma.sync.aligned.m16n8k8.row.col.f32.tf32.tf32.f32 "
        "{%0,%1,%2,%3},{%4,%5,%6,%7},{%8,%9},{%0,%1,%2,%3};"
        : "+f"(d[0]), "+f"(d[1]), "+f"(d[2]), "+f"(d[3])
        : "r"(a[0]), "r"(a[1]), "r"(a[2]), "r"(a[3]), "r"(b[0]), "r"(b[1]));
}

__device__ __forceinline__ float gelu_exact(float v) {
    return 0.5f * v * (1.0f + erff(v * 0.70710678118654752f));
}

// token (wi,t) -> rolled source/dest offset in (B,D,H,W,C) layout
__device__ __forceinline__ size_t roll_offset(int wi, int t) {
    int wB = wi & 7, hB = (wi >> 3) & 7, dB = (wi >> 6) & 3, bb = wi >> 8;
    int dt = t >> 6, ht = (t >> 3) & 7, wt = t & 7;
    int ds = (dB * 2 + dt + 1) & 7;
    int hs = (hB * 8 + ht + 4) & 63;
    int ws = (wB * 8 + wt + 4) & 63;
    return (size_t)((((bb * 8 + ds) * 64 + hs) * 64 + ws)) * CH;
}

// ---------------- K1: LN1 + roll + window partition ----------------
__global__ void k_ln1(const float* __restrict__ x, const float* __restrict__ g,
                      const float* __restrict__ b) {
    int warp = (blockIdx.x * blockDim.x + threadIdx.x) >> 5;
    int lane = threadIdx.x & 31;
    if (warp >= NTOK) return;
    int wi = warp >> 7, t = warp & 127;
    const float* src = x + roll_offset(wi, t);
    float v0 = 0, v1 = 0, v2 = 0, v3 = 0, s = 0, sq = 0;
    if (lane < 30) {
        float4 f = *(const float4*)(src + lane * 4);
        v0 = f.x; v1 = f.y; v2 = f.z; v3 = f.w;
        s  = v0 + v1 + v2 + v3;
        sq = v0 * v0 + v1 * v1 + v2 * v2 + v3 * v3;
    }
#pragma unroll
    for (int o = 16; o; o >>= 1) {
        s  += __shfl_xor_sync(0xffffffffu, s, o);
        sq += __shfl_xor_sync(0xffffffffu, sq, o);
    }
    float mean = s * (1.0f / 120.0f);
    float var  = sq * (1.0f / 120.0f) - mean * mean;
    float r = rsqrtf(var + 1e-5f);
    if (lane < 30) {
        int c = lane * 4;
        float* dst = g_xw + (size_t)warp * CH + c;
        dst[0] = (v0 - mean) * r * g[c]     + b[c];
        dst[1] = (v1 - mean) * r * g[c + 1] + b[c + 1];
        dst[2] = (v2 - mean) * r * g[c + 2] + b[c + 2];
        dst[3] = (v3 - mean) * r * g[c + 3] + b[c + 3];
    }
}

// ---------------- LN2 (plain layout) ----------------
__global__ void k_ln2(const float* __restrict__ g, const float* __restrict__ b) {
    int warp = (blockIdx.x * blockDim.x + threadIdx.x) >> 5;
    int lane = threadIdx.x & 31;
    if (warp >= NTOK) return;
    const float* src = g_xres + (size_t)warp * CH;
    float v0 = 0, v1 = 0, v2 = 0, v3 = 0, s = 0, sq = 0;
    if (lane < 30) {
        float4 f = *(const float4*)(src + lane * 4);
        v0 = f.x; v1 = f.y; v2 = f.z; v3 = f.w;
        s  = v0 + v1 + v2 + v3;
        sq = v0 * v0 + v1 * v1 + v2 * v2 + v3 * v3;
    }
#pragma unroll
    for (int o = 16; o; o >>= 1) {
        s  += __shfl_xor_sync(0xffffffffu, s, o);
        sq += __shfl_xor_sync(0xffffffffu, sq, o);
    }
    float mean = s * (1.0f / 120.0f);
    float var  = sq * (1.0f / 120.0f) - mean * mean;
    float r = rsqrtf(var + 1e-5f);
    if (lane < 30) {
        int c = lane * 4;
        float* dst = g_z + (size_t)warp * CH + c;
        dst[0] = (v0 - mean) * r * g[c]     + b[c];
        dst[1] = (v1 - mean) * r * g[c + 1] + b[c + 1];
        dst[2] = (v2 - mean) * r * g[c + 2] + b[c + 2];
        dst[3] = (v3 - mean) * r * g[c + 3] + b[c + 3];
    }
}

// ---------------- tf32 tensor-core GEMM: out = A @ B^T + epilogue --------
// Block 128x128, 8 warps (2x4), warp tile 64x32, mma m16n8k8 tf32.
// MODE 0: qkv self (A=g_xw, K=120, N=360, out [win][n][128] via smem stage)
// MODE 1: qkv mut  (A=g_xw + pos(extra), rest same as MODE 0)
// MODE 2: proj     (A=g_xout [win][240][128] k-major, K=240, N=120,
//                   epi: scatter(roll) + x(extra) add -> g_xres row-major)
// MODE 3: mlp1     (B split fc11/fc12, K=120, N=480, out row-major)
// MODE 4: mlp2     (A = gelu-gate from g_h (phys 480), K=240, N=120,
//                   epi: + g_xres(extra) -> d_out row-major)
template <int KD, int MODE>
__global__ void __launch_bounds__(256) k_gemm(
    const float* __restrict__ A, const float* __restrict__ B1,
    const float* __restrict__ B2, const float* __restrict__ bias,
    const float* __restrict__ bias2, const float* __restrict__ extra,
    float* __restrict__ out, int Ntot) {
    __shared__ float sm[3072];
    float* As = sm;            // [128][12] padded, [m][k]
    float* Bs = sm + 1536;     // [128][12] padded, [n][k]
    int tid = threadIdx.x;
    int m0 = blockIdx.x * 128;
    int n0 = blockIdx.y * 128;
    int win = m0 >> 7;
    int warp = tid >> 5, lane = tid & 31;
    int g = lane >> 2, th = lane & 3;
    int wm = (warp & 1) * 64;
    int wn = (warp >> 1) * 32;
    int lr = tid >> 1;          // load row 0..127
    int lc = (tid & 1) * 4;     // load col offset (0 or 4)

    float d[4][4][4];
#pragma unroll
    for (int i = 0; i < 4; i++)
#pragma unroll
        for (int j = 0; j < 4; j++)
#pragma unroll
            for (int r = 0; r < 4; r++) d[i][j][r] = 0.0f;

    int am = m0 + lr;
    int bn = n0 + lr;
    bool bvalid = bn < Ntot;
    const float* bsrc;
    if (MODE == 3) {
        bsrc = (bn < 240) ? (B1 + (size_t)bn * KD)
                          : (B2 + (size_t)(bn - 240) * KD);
    } else {
        bsrc = B1 + (size_t)(bvalid ? bn : 0) * KD;
    }

    for (int k0 = 0; k0 < KD; k0 += 8) {
        // ---- A tile ----
        if (MODE == 2) {
            int kk = tid >> 5;
            int mc = (tid & 31) * 4;
            float4 av = *(const float4*)(A + ((size_t)win * 240 + k0 + kk) * 128 + mc);
            __syncthreads();
            As[(mc + 0) * 12 + kk] = f2tf32(av.x);
            As[(mc + 1) * 12 + kk] = f2tf32(av.y);
            As[(mc + 2) * 12 + kk] = f2tf32(av.z);
            As[(mc + 3) * 12 + kk] = f2tf32(av.w);
        } else {
            float4 av;
            if (MODE == 4) {
                const float* hp = A + (size_t)am * 480 + k0 + lc;
                float4 h1 = *(const float4*)hp;
                float4 h2 = *(const float4*)(hp + 240);
                av.x = gelu_exact(h1.x) * h2.x;
                av.y = gelu_exact(h1.y) * h2.y;
                av.z = gelu_exact(h1.z) * h2.z;
                av.w = gelu_exact(h1.w) * h2.w;
            } else {
                av = *(const float4*)(A + (size_t)am * KD + k0 + lc);
                if (MODE == 1) {
                    int tt = am & 63;
                    float4 p = *(const float4*)(extra + (size_t)tt * CH + k0 + lc);
                    av.x += p.x; av.y += p.y; av.z += p.z; av.w += p.w;
                }
            }
            av.x = f2tf32(av.x); av.y = f2tf32(av.y);
            av.z = f2tf32(av.z); av.w = f2tf32(av.w);
            __syncthreads();
            *(float4*)&As[lr * 12 + lc] = av;
        }
        // ---- B tile ----
        {
            float4 bv = make_float4(0.f, 0.f, 0.f, 0.f);
            if (bvalid) bv = *(const float4*)(bsrc + k0 + lc);
            bv.x = f2tf32(bv.x); bv.y = f2tf32(bv.y);
            bv.z = f2tf32(bv.z); bv.w = f2tf32(bv.w);
            *(float4*)&Bs[lr * 12 + lc] = bv;
        }
        __syncthreads();

        // ---- fragments + mma ----
        uint32_t a[4][4], b[4][2];
#pragma unroll
        for (int i = 0; i < 4; i++) {
            const float* base = As + (wm + i * 16 + g) * 12;
            a[i][0] = __float_as_uint(base[th]);
            a[i][1] = __float_as_uint(base[96 + th]);      // +8 rows * 12
            a[i][2] = __float_as_uint(base[th + 4]);
            a[i][3] = __float_as_uint(base[96 + th + 4]);
        }
#pragma unroll
        for (int j = 0; j < 4; j++) {
            const float* base = Bs + (wn + j * 8 + g) * 12;
            b[j][0] = __float_as_uint(base[th]);
            b[j][1] = __float_as_uint(base[th + 4]);
        }
#pragma unroll
        for (int i = 0; i < 4; i++)
#pragma unroll
            for (int j = 0; j < 4; j++) mma_tf32(d[i][j], a[i], b[j]);
    }

    if (MODE == 0 || MODE == 1) {
        // staged transposed epilogue: write [n][128] tile of window `win`
        __syncthreads();
        int nrow = tid >> 4;            // 0..15
        int mcol = (tid & 15) * 8;
#pragma unroll 1
        for (int c = 0; c < 8; c++) {
            if ((wn >> 5) == (c >> 1)) {
                int jbase = (c & 1) * 2;
#pragma unroll
                for (int jj = 0; jj < 2; jj++) {
                    int j = jbase + jj;
#pragma unroll
                    for (int i = 0; i < 4; i++)
#pragma unroll
                        for (int r = 0; r < 4; r++) {
                            int nl = j * 8 + 2 * th + (r & 1) - (c & 1) * 16;
                            int m  = wm + i * 16 + g + (r >> 1) * 8;
                            sm[nl * 128 + m] = d[i][j][r];
                        }
                }
            }
            __syncthreads();
            int n = n0 + c * 16 + nrow;
            if (n < Ntot) {
                float bz = bias[n];
                float4 x1 = *(float4*)&sm[nrow * 128 + mcol];
                float4 x2 = *(float4*)&sm[nrow * 128 + mcol + 4];
                x1.x += bz; x1.y += bz; x1.z += bz; x1.w += bz;
                x2.x += bz; x2.y += bz; x2.z += bz; x2.w += bz;
                float* op = out + ((size_t)win * 360 + n) * 128 + mcol;
                *(float4*)op = x1;
                *(float4*)(op + 4) = x2;
            }
            __syncthreads();
        }
        return;
    }

    // float2 epilogues (MODE 2/3/4)
#pragma unroll
    for (int i = 0; i < 4; i++)
#pragma unroll
        for (int rh = 0; rh < 2; rh++) {
            int m = m0 + wm + i * 16 + g + rh * 8;
            size_t drow;
            if (MODE == 2) {
                drow = roll_offset(m >> 7, m & 127);
            } else {
                drow = (size_t)m * Ntot;
            }
#pragma unroll
            for (int j = 0; j < 4; j++) {
                int n = n0 + wn + j * 8 + 2 * th;
                if (n >= Ntot) continue;
                float2 v = make_float2(d[i][j][rh * 2], d[i][j][rh * 2 + 1]);
                if (MODE == 2) {
                    const float* e = extra + drow + n;
                    v.x += bias[n] + e[0];
                    v.y += bias[n + 1] + e[1];
                } else if (MODE == 3) {
                    const float* bp = (n < 240) ? (bias + n) : (bias2 + n - 240);
                    v.x += bp[0];
                    v.y += bp[1];
                } else {  // MODE 4
                    const float* e = extra + (size_t)m * 120 + n;
                    v.x += bias[n] + e[0];
                    v.y += bias[n + 1] + e[1];
                }
                *(float2*)(out + drow + n) = v;
            }
        }
}

// ---------------- K4: attention (self + mutual), block = (window, head) ----
__global__ void __launch_bounds__(128) k_attn(const float* __restrict__ rpb) {
    __shared__ float sk[128 * 24];
    __shared__ float sv[128 * 24];
    __shared__ float srpb[675];
    __shared__ int   sg[128];

    int wi = blockIdx.x, h = blockIdx.y;
    int t = threadIdx.x;

    for (int i = t; i < 675; i += 128) srpb[i] = rpb[i * 6 + h];

    // token / window coordinates
    int dt = t >> 6, ht = (t >> 3) & 7, wt = t & 7;
    int dB = (wi >> 6) & 3, hB = (wi >> 3) & 7, wB = wi & 7;
    int dd = dB * 2 + dt, hh = hB * 8 + ht, ww = wB * 8 + wt;
    int gd = (dd < 6) ? 0 : ((dd < 7) ? 1 : 2);
    int gh = (hh < 56) ? 0 : ((hh < 60) ? 1 : 2);
    int gw = (ww < 56) ? 0 : ((ww < 60) ? 1 : 2);
    int grp = gd * 9 + gh * 3 + gw;
    int gd0 = (dB * 2 < 6) ? 0 : 1;
    int grp0 = gd0 * 9 + gh * 3 + gw;
    int ccode = dt * 225 + ht * 15 + wt;
    sg[t] = ccode | (grp << 10) | (grp0 << 16);
    int rbase = (dt + 1) * 225 + (ht + 7) * 15 + (wt + 7);

    // ---- self QKV load (coalesced) ----
    const float* Q = g_qkv_s + (size_t)wi * 360 * 128;
    ull q2[10];
#pragma unroll
    for (int d = 0; d < 10; d++) {
        float lo = Q[(h * 20 + 2 * d) * 128 + t] * SCALE_F;
        float hi = Q[(h * 20 + 2 * d + 1) * 128 + t] * SCALE_F;
        q2[d] = pack2(lo, hi);
    }
#pragma unroll
    for (int d = 0; d < 20; d++) {
        sk[t * 24 + d] = Q[(120 + h * 20 + d) * 128 + t];
        sv[t * 24 + d] = Q[(240 + h * 20 + d) * 128 + t];
    }
    __syncthreads();

    ull o2[10];
#pragma unroll
    for (int d = 0; d < 10; d++) o2[d] = 0ULL;
    float sum = 0.f;

#pragma unroll 2
    for (int m = 0; m < 128; m++) {
        int s = sg[m];
        const ulonglong2* kr = (const ulonglong2*)(sk + m * 24);
        ulonglong2 k0 = kr[0], k1 = kr[1], k2 = kr[2], k3 = kr[3], k4 = kr[4];
        ull aA = 0ULL, aB = 0ULL;
        fma2(aA, q2[0], k0.x); fma2(aB, q2[1], k0.y);
        fma2(aA, q2[2], k1.x); fma2(aB, q2[3], k1.y);
        fma2(aA, q2[4], k2.x); fma2(aB, q2[5], k2.y);
        fma2(aA, q2[6], k3.x); fma2(aB, q2[7], k3.y);
        fma2(aA, q2[8], k4.x); fma2(aB, q2[9], k4.y);
        float2 fa = u2f(aA), fb = u2f(aB);
        float logit = (fa.x + fa.y) + (fb.x + fb.y) + srpb[rbase - (s & 1023)];
        float p = (((s >> 10) & 31) == grp) ? __expf(logit) : 0.f;
        sum += p;
        ull pd = pack2(p, p);
        const ulonglong2* vr = (const ulonglong2*)(sv + m * 24);
        ulonglong2 v0 = vr[0], v1 = vr[1], v2 = vr[2], v3 = vr[3], v4 = vr[4];
        fma2(o2[0], pd, v0.x); fma2(o2[1], pd, v0.y);
        fma2(o2[2], pd, v1.x); fma2(o2[3], pd, v1.y);
        fma2(o2[4], pd, v2.x); fma2(o2[5], pd, v2.y);
        fma2(o2[6], pd, v3.x); fma2(o2[7], pd, v3.y);
        fma2(o2[8], pd, v4.x); fma2(o2[9], pd, v4.y);
    }
    {
        float inv = 1.0f / sum;
        float* ob = g_xout + ((size_t)wi * 240 + 120 + h * 20) * 128 + t;
#pragma unroll
        for (int d = 0; d < 10; d++) {
            float2 f = u2f(o2[d]);
            ob[(2 * d) * 128]     = f.x * inv;
            ob[(2 * d + 1) * 128] = f.y * inv;
        }
    }
    __syncthreads();  // done with sk/sv before overwrite

    // ---- mutual attention ----
    int qrow = t ^ 64;
    int mb   = (t < 64) ? 0 : 64;
    const float* Qm = g_qkv_m + (size_t)wi * 360 * 128;
#pragma unroll
    for (int d = 0; d < 20; d++) {
        sk[t * 24 + d] = Qm[(120 + h * 20 + d) * 128 + t];
        sv[t * 24 + d] = Qm[(240 + h * 20 + d) * 128 + t];
    }
    ull q2b[10];
#pragma unroll
    for (int d = 0; d < 10; d++) {
        float lo = Qm[(h * 20 + 2 * d) * 128 + qrow] * SCALE_F;
        float hi = Qm[(h * 20 + 2 * d + 1) * 128 + qrow] * SCALE_F;
        q2b[d] = pack2(lo, hi);
    }
    __syncthreads();

#pragma unroll
    for (int d = 0; d < 10; d++) o2[d] = 0ULL;
    sum = 0.f;
    int mygrp0 = (sg[t & 63] >> 16) & 31;

#pragma unroll 2
    for (int m = 0; m < 64; m++) {
        int s = sg[m];
        const ulonglong2* kr = (const ulonglong2*)(sk + (mb + m) * 24);
        ulonglong2 k0 = kr[0], k1 = kr[1], k2 = kr[2], k3 = kr[3], k4 = kr[4];
        ull aA = 0ULL, aB = 0ULL;
        fma2(aA, q2b[0], k0.x); fma2(aB, q2b[1], k0.y);
        fma2(aA, q2b[2], k1.x); fma2(aB, q2b[3], k1.y);
        fma2(aA, q2b[4], k2.x); fma2(aB, q2b[5], k2.y);
        fma2(aA, q2b[6], k3.x); fma2(aB, q2b[7], k3.y);
        fma2(aA, q2b[8], k4.x); fma2(aB, q2b[9], k4.y);
        float2 fa = u2f(aA), fb = u2f(aB);
        float logit = (fa.x + fa.y) + (fb.x + fb.y);
        float p = (((s >> 16) & 31) == mygrp0) ? __expf(logit) : 0.f;
        sum += p;
        ull pd = pack2(p, p);
        const ulonglong2* vr = (const ulonglong2*)(sv + (mb + m) * 24);
        ulonglong2 v0 = vr[0], v1 = vr[1], v2 = vr[2], v3 = vr[3], v4 = vr[4];
        fma2(o2[0], pd, v0.x); fma2(o2[1], pd, v0.y);
        fma2(o2[2], pd, v1.x); fma2(o2[3], pd, v1.y);
        fma2(o2[4], pd, v2.x); fma2(o2[5], pd, v2.y);
        fma2(o2[6], pd, v3.x); fma2(o2[7], pd, v3.y);
        fma2(o2[8], pd, v4.x); fma2(o2[9], pd, v4.y);
    }
    {
        float inv = 1.0f / sum;
        float* ob = g_xout + ((size_t)wi * 240 + h * 20) * 128 + t;
#pragma unroll
        for (int d = 0; d < 10; d++) {
            float2 f = u2f(o2[d]);
            ob[(2 * d) * 128]     = f.x * inv;
            ob[(2 * d + 1) * 128] = f.y * inv;
        }
    }
}

// ---------------- launch ----------------
extern "C" void kernel_launch(void* const* d_in, const int* in_sizes, int n_in,
                              void* d_out, int out_size) {
    const float* x          = (const float*)d_in[0];
    const float* g1         = (const float*)d_in[2];
    const float* b1         = (const float*)d_in[3];
    const float* qkv_self_w = (const float*)d_in[4];
    const float* qkv_self_b = (const float*)d_in[5];
    const float* qkv_mut_w  = (const float*)d_in[6];
    const float* qkv_mut_b  = (const float*)d_in[7];
    const float* proj_w     = (const float*)d_in[8];
    const float* proj_b     = (const float*)d_in[9];
    const float* rpb        = (const float*)d_in[10];
    const float* pos        = (const float*)d_in[11];
    const float* g2         = (const float*)d_in[12];
    const float* b2         = (const float*)d_in[13];
    const float* fc11_w     = (const float*)d_in[14];
    const float* fc11_b     = (const float*)d_in[15];
    const float* fc12_w     = (const float*)d_in[16];
    const float* fc12_b     = (const float*)d_in[17];
    const float* fc2_w      = (const float*)d_in[18];
    const float* fc2_b      = (const float*)d_in[19];
    float* out = (float*)d_out;

    float* xw   = nullptr; cudaGetSymbolAddress((void**)&xw,   g_xw);
    float* qkvs = nullptr; cudaGetSymbolAddress((void**)&qkvs, g_qkv_s);
    float* qkvm = nullptr; cudaGetSymbolAddress((void**)&qkvm, g_qkv_m);
    float* xo   = nullptr; cudaGetSymbolAddress((void**)&xo,   g_xout);
    float* xres = nullptr; cudaGetSymbolAddress((void**)&xres, g_xres);
    float* zb   = nullptr; cudaGetSymbolAddress((void**)&zb,   g_z);
    float* hb   = nullptr; cudaGetSymbolAddress((void**)&hb,   g_h);

    // 1. LN1 + roll + window partition
    k_ln1<<<NTOK / 8, 256>>>(x, g1, b1);
    // 2. QKV self (-> [win][360][128])
    k_gemm<120, 0><<<dim3(NTOK / 128, 3), 256>>>(
        xw, qkv_self_w, nullptr, qkv_self_b, nullptr, nullptr, qkvs, 360);
    // 3. QKV mutual (+ pos bias on A, -> [win][360][128])
    k_gemm<120, 1><<<dim3(NTOK / 128, 3), 256>>>(
        xw, qkv_mut_w, nullptr, qkv_mut_b, nullptr, pos, qkvm, 360);
    // 4. attention (-> g_xout [win][240][128])
    k_attn<<<dim3(NWIN, 6), 128>>>(rpb);
    // 5. proj + window-reverse + roll-back + shortcut add
    k_gemm<240, 2><<<dim3(NTOK / 128, 1), 256>>>(
        xo, proj_w, nullptr, proj_b, nullptr, x, xres, 120);
    // 6. LN2
    k_ln2<<<NTOK / 8, 256>>>(g2, b2);
    // 7. fc11 | fc12
    k_gemm<120, 3><<<dim3(NTOK / 128, 4), 256>>>(
        zb, fc11_w, fc12_w, fc11_b, fc12_b, nullptr, hb, 480);
    // 8. gelu-gate + fc2 + residual -> out
    k_gemm<240, 4><<<dim3(NTOK / 128, 1), 256>>>(
        hb, fc2_w, nullptr, fc2_b, nullptr, xres, out, 120);
}

// round 13
// speedup vs baseline: 2.0116x; 1.1870x over previous
#include <cuda_runtime.h>
#include <math.h>
#include <stdint.h>

typedef unsigned long long ull;

// ---------------- problem constants ----------------
constexpr int CH   = 120;
constexpr int NWIN = 1024;          // total windows (4 * 4 * 8 * 8)
constexpr int NTOK = NWIN * 128;    // 131072
constexpr float SCALE_F = 0.22360679774997896f;  // 20^-0.5

// ---------------- scratch ----------------
__device__ float g_xw   [(size_t)NTOK * CH];    // LN1'd (tf32-rounded)
__device__ float g_xwm  [(size_t)NTOK * CH];    // g_xw + pos (tf32-rounded)
__device__ float g_qkv_s[(size_t)NTOK * 360];   // layout [win][360][128]
__device__ float g_qkv_m[(size_t)NTOK * 360];   // layout [win][360][128]
__device__ float g_xout [(size_t)NTOK * 240];   // [win][240][128] (tf32-rounded)
__device__ float g_xres [(size_t)NTOK * CH];    // x + attn branch (exact)
__device__ float g_z    [(size_t)NTOK * CH];    // LN2 out (tf32-rounded)
__device__ float g_h    [(size_t)NTOK * 480];   // fc11|fc12 pre-activations
__device__ float g_act  [(size_t)NTOK * 240];   // gelu gate (tf32-rounded)
__device__ float g_wts  [259200];               // tf32-rounded weights

// weight buffer offsets
constexpr int W_QS  = 0;        // qkv_self_w 43200
constexpr int W_QM  = 43200;    // qkv_mut_w  43200
constexpr int W_PR  = 86400;    // proj_w     28800
constexpr int W_F11 = 115200;   // fc11_w     57600
constexpr int W_F12 = 172800;   // fc12_w     57600
constexpr int W_F2  = 230400;   // fc2_w      28800

// ---------------- helpers ----------------
__device__ __forceinline__ void fma2(ull& d, ull a, ull b) {
    asm("fma.rn.f32x2 %0, %1, %2, %0;" : "+l"(d) : "l"(a), "l"(b));
}
__device__ __forceinline__ ull pack2(float lo, float hi) {
    ull r; asm("mov.b64 %0, {%1, %2};" : "=l"(r) : "f"(lo), "f"(hi)); return r;
}
__device__ __forceinline__ float2 u2f(ull v) {
    float2 f; asm("mov.b64 {%0, %1}, %2;" : "=f"(f.x), "=f"(f.y) : "l"(v)); return f;
}
__device__ __forceinline__ float f2tf32(float f) {
    uint32_t r; asm("cvt.rna.tf32.f32 %0, %1;" : "=r"(r) : "f"(f));
    return __uint_as_float(r);
}
__device__ __forceinline__ void mma_tf32(float* d, const uint32_t* a,
                                         const uint32_t* b) {
    asm("mma.sync.aligned.m16n8k8.row.col.f32.tf32.tf32.f32 "
        "{%0,%1,%2,%3},{%4,%5,%6,%7},{%8,%9},{%0,%1,%2,%3};"
        : "+f"(d[0]), "+f"(d[1]), "+f"(d[2]), "+f"(d[3])
        : "r"(a[0]), "r"(a[1]), "r"(a[2]), "r"(a[3]), "r"(b[0]), "r"(b[1]));
}
__device__ __forceinline__ void cp16(float* smem_dst, const float* gsrc,
                                     bool pred) {
    uint32_t sa = (uint32_t)__cvta_generic_to_shared(smem_dst);
    int sz = pred ? 16 : 0;
    asm volatile("cp.async.ca.shared.global [%0], [%1], 16, %2;"
                 :: "r"(sa), "l"(gsrc), "r"(sz));
}
#define CP_COMMIT() asm volatile("cp.async.commit_group;")

__device__ __forceinline__ float gelu_exact(float v) {
    return 0.5f * v * (1.0f + erff(v * 0.70710678118654752f));
}

// token (wi,t) -> rolled source/dest offset in (B,D,H,W,C) layout
__device__ __forceinline__ size_t roll_offset(int wi, int t) {
    int wB = wi & 7, hB = (wi >> 3) & 7, dB = (wi >> 6) & 3, bb = wi >> 8;
    int dt = t >> 6, ht = (t >> 3) & 7, wt = t & 7;
    int ds = (dB * 2 + dt + 1) & 7;
    int hs = (hB * 8 + ht + 4) & 63;
    int ws = (wB * 8 + wt + 4) & 63;
    return (size_t)((((bb * 8 + ds) * 64 + hs) * 64 + ws)) * CH;
}

// ---------------- K0: round all weights to tf32 once per launch ----------
__global__ void k_wcvt(const float* __restrict__ qs, const float* __restrict__ qm,
                       const float* __restrict__ pr, const float* __restrict__ f11,
                       const float* __restrict__ f12, const float* __restrict__ f2) {
    int i4 = blockIdx.x * blockDim.x + threadIdx.x;
    if (i4 >= 64800) return;
    int i = i4 * 4;
    const float* src;
    int off;
    if (i < 43200)       { src = qs;  off = i; }
    else if (i < 86400)  { src = qm;  off = i - 43200; }
    else if (i < 115200) { src = pr;  off = i - 86400; }
    else if (i < 172800) { src = f11; off = i - 115200; }
    else if (i < 230400) { src = f12; off = i - 172800; }
    else                 { src = f2;  off = i - 230400; }
    float4 v = *(const float4*)(src + off);
    v.x = f2tf32(v.x); v.y = f2tf32(v.y);
    v.z = f2tf32(v.z); v.w = f2tf32(v.w);
    *(float4*)(g_wts + i) = v;
}

// ---------------- K1: LN1 + roll + window partition (+pos variant) -------
__global__ void k_ln1(const float* __restrict__ x, const float* __restrict__ g,
                      const float* __restrict__ b, const float* __restrict__ pos) {
    int warp = (blockIdx.x * blockDim.x + threadIdx.x) >> 5;
    int lane = threadIdx.x & 31;
    if (warp >= NTOK) return;
    int wi = warp >> 7, t = warp & 127;
    const float* src = x + roll_offset(wi, t);
    float v0 = 0, v1 = 0, v2 = 0, v3 = 0, s = 0, sq = 0;
    if (lane < 30) {
        float4 f = *(const float4*)(src + lane * 4);
        v0 = f.x; v1 = f.y; v2 = f.z; v3 = f.w;
        s  = v0 + v1 + v2 + v3;
        sq = v0 * v0 + v1 * v1 + v2 * v2 + v3 * v3;
    }
#pragma unroll
    for (int o = 16; o; o >>= 1) {
        s  += __shfl_xor_sync(0xffffffffu, s, o);
        sq += __shfl_xor_sync(0xffffffffu, sq, o);
    }
    float mean = s * (1.0f / 120.0f);
    float var  = sq * (1.0f / 120.0f) - mean * mean;
    float r = rsqrtf(var + 1e-5f);
    if (lane < 30) {
        int c = lane * 4;
        float y0 = (v0 - mean) * r * g[c]     + b[c];
        float y1 = (v1 - mean) * r * g[c + 1] + b[c + 1];
        float y2 = (v2 - mean) * r * g[c + 2] + b[c + 2];
        float y3 = (v3 - mean) * r * g[c + 3] + b[c + 3];
        float* dst = g_xw + (size_t)warp * CH + c;
        dst[0] = f2tf32(y0); dst[1] = f2tf32(y1);
        dst[2] = f2tf32(y2); dst[3] = f2tf32(y3);
        float4 pv = *(const float4*)(pos + (size_t)(t & 63) * CH + c);
        float* dm = g_xwm + (size_t)warp * CH + c;
        dm[0] = f2tf32(y0 + pv.x); dm[1] = f2tf32(y1 + pv.y);
        dm[2] = f2tf32(y2 + pv.z); dm[3] = f2tf32(y3 + pv.w);
    }
}

// ---------------- LN2 (plain layout, tf32-rounded out) ----------------
__global__ void k_ln2(const float* __restrict__ g, const float* __restrict__ b) {
    int warp = (blockIdx.x * blockDim.x + threadIdx.x) >> 5;
    int lane = threadIdx.x & 31;
    if (warp >= NTOK) return;
    const float* src = g_xres + (size_t)warp * CH;
    float v0 = 0, v1 = 0, v2 = 0, v3 = 0, s = 0, sq = 0;
    if (lane < 30) {
        float4 f = *(const float4*)(src + lane * 4);
        v0 = f.x; v1 = f.y; v2 = f.z; v3 = f.w;
        s  = v0 + v1 + v2 + v3;
        sq = v0 * v0 + v1 * v1 + v2 * v2 + v3 * v3;
    }
#pragma unroll
    for (int o = 16; o; o >>= 1) {
        s  += __shfl_xor_sync(0xffffffffu, s, o);
        sq += __shfl_xor_sync(0xffffffffu, sq, o);
    }
    float mean = s * (1.0f / 120.0f);
    float var  = sq * (1.0f / 120.0f) - mean * mean;
    float r = rsqrtf(var + 1e-5f);
    if (lane < 30) {
        int c = lane * 4;
        float* dst = g_z + (size_t)warp * CH + c;
        dst[0] = f2tf32((v0 - mean) * r * g[c]     + b[c]);
        dst[1] = f2tf32((v1 - mean) * r * g[c + 1] + b[c + 1]);
        dst[2] = f2tf32((v2 - mean) * r * g[c + 2] + b[c + 2]);
        dst[3] = f2tf32((v3 - mean) * r * g[c + 3] + b[c + 3]);
    }
}

// ---------------- gated-gelu elementwise (tf32-rounded out) ----------------
__global__ void k_act() {
    int idx = blockIdx.x * blockDim.x + threadIdx.x;
    if (idx >= NTOK * 60) return;
    int m = idx / 60, c4 = (idx % 60) * 4;
    const float* hp = g_h + (size_t)m * 480 + c4;
    float4 h1 = *(const float4*)hp;
    float4 h2 = *(const float4*)(hp + 240);
    float4 o;
    o.x = f2tf32(gelu_exact(h1.x) * h2.x);
    o.y = f2tf32(gelu_exact(h1.y) * h2.y);
    o.z = f2tf32(gelu_exact(h1.z) * h2.z);
    o.w = f2tf32(gelu_exact(h1.w) * h2.w);
    *(float4*)(g_act + (size_t)m * 240 + c4) = o;
}

// ---------------- tf32 tensor-core GEMM, cp.async 3-stage pipeline -------
// Block 128x128, 8 warps (2x4), warp tile 64x32, mma m16n8k8 tf32.
// All A/B sources are pre-rounded to tf32 -> no cvt in mainloop.
// MODE 0: plain A row-major [M][KD]; MODE 2: A k-major [win][240][128].
// EPI 3 also selects the split fc11/fc12 B source.
// OUTT 1: out [win][n][128] staged transpose (qkv)
// EPI: 0 = bias only, 2 = roll scatter + extra, 3 = split bias/weights,
//      4 = + extra row-major (mlp2 -> d_out)
template <int KD, int MODE, int OUTT, int EPI>
__global__ void __launch_bounds__(256) k_gemm(
    const float* __restrict__ A, const float* __restrict__ B1,
    const float* __restrict__ B2, const float* __restrict__ bias,
    const float* __restrict__ bias2, const float* __restrict__ extra,
    float* __restrict__ out, int Ntot) {
    constexpr int S = KD / 8;
    __shared__ float sm[3 * 3072];
    int tid = threadIdx.x;
    int m0 = blockIdx.x * 128;
    int n0 = blockIdx.y * 128;
    int win = m0 >> 7;
    int warp = tid >> 5, lane = tid & 31;
    int g = lane >> 2, th = lane & 3;
    int wm = (warp & 1) * 64;
    int wn = (warp >> 1) * 32;
    int lr = tid >> 1;          // load row 0..127
    int lc = (tid & 1) * 4;     // load col offset (0 or 4)
    int kk = tid >> 5;          // MODE2: k row 0..7
    int mc = (tid & 31) * 4;    // MODE2: m col

    float d[4][4][4];
#pragma unroll
    for (int i = 0; i < 4; i++)
#pragma unroll
        for (int j = 0; j < 4; j++)
#pragma unroll
            for (int r = 0; r < 4; r++) d[i][j][r] = 0.0f;

    int am = m0 + lr;
    int bn = n0 + lr;
    bool bvalid = bn < Ntot;
    const float* bsrc;
    if (EPI == 3) {
        bsrc = (bn < 240) ? (B1 + (size_t)bn * KD)
                          : (B2 + (size_t)(bn - 240) * KD);
    } else {
        bsrc = B1 + (size_t)(bvalid ? bn : 0) * KD;
    }

    auto issue = [&](int s, int off) {
        float* base = sm + off;
        int k0 = s * 8;
        if (MODE == 2) {
            cp16(base + kk * 132 + mc,
                 A + ((size_t)win * 240 + k0 + kk) * 128 + mc, true);
        } else {
            cp16(base + lr * 12 + lc, A + (size_t)am * KD + k0 + lc, true);
        }
        cp16(base + 1536 + lr * 12 + lc, bsrc + k0 + lc, bvalid);
        CP_COMMIT();
    };

    issue(0, 0);
    issue(1, 3072);

    int c_off = 0, p_off = 2 * 3072;
#pragma unroll 1
    for (int s = 0; s < S; s++) {
        if (s + 1 < S) asm volatile("cp.async.wait_group 1;");
        else           asm volatile("cp.async.wait_group 0;");
        __syncthreads();

        const float* As = sm + c_off;
        const float* Bs = As + 1536;
        uint32_t a[4][4], b[4][2];
#pragma unroll
        for (int i = 0; i < 4; i++) {
            int m1 = wm + i * 16 + g;
            if (MODE == 2) {
                a[i][0] = __float_as_uint(As[th * 132 + m1]);
                a[i][1] = __float_as_uint(As[th * 132 + m1 + 8]);
                a[i][2] = __float_as_uint(As[(th + 4) * 132 + m1]);
                a[i][3] = __float_as_uint(As[(th + 4) * 132 + m1 + 8]);
            } else {
                const float* base = As + m1 * 12;
                a[i][0] = __float_as_uint(base[th]);
                a[i][1] = __float_as_uint(base[96 + th]);
                a[i][2] = __float_as_uint(base[th + 4]);
                a[i][3] = __float_as_uint(base[96 + th + 4]);
            }
        }
#pragma unroll
        for (int j = 0; j < 4; j++) {
            const float* base = Bs + (wn + j * 8 + g) * 12;
            b[j][0] = __float_as_uint(base[th]);
            b[j][1] = __float_as_uint(base[th + 4]);
        }
#pragma unroll
        for (int i = 0; i < 4; i++)
#pragma unroll
            for (int j = 0; j < 4; j++) mma_tf32(d[i][j], a[i], b[j]);

        if (s + 2 < S) issue(s + 2, p_off);
        c_off = (c_off == 6144) ? 0 : c_off + 3072;
        p_off = (p_off == 6144) ? 0 : p_off + 3072;
    }

    if (OUTT == 1) {
        // staged transposed epilogue: write [n][128] tile of window `win`
        __syncthreads();
        int nrow = tid >> 4;            // 0..15
        int mcol = (tid & 15) * 8;
#pragma unroll 1
        for (int c = 0; c < 8; c++) {
            if ((wn >> 5) == (c >> 1)) {
                int jbase = (c & 1) * 2;
#pragma unroll
                for (int jj = 0; jj < 2; jj++) {
                    int j = jbase + jj;
#pragma unroll
                    for (int i = 0; i < 4; i++)
#pragma unroll
                        for (int r = 0; r < 4; r++) {
                            int nl = j * 8 + 2 * th + (r & 1) - (c & 1) * 16;
                            int m  = wm + i * 16 + g + (r >> 1) * 8;
                            sm[nl * 128 + m] = d[i][j][r];
                        }
                }
            }
            __syncthreads();
            int n = n0 + c * 16 + nrow;
            if (n < Ntot) {
                float bz = bias[n];
                float4 x1 = *(float4*)&sm[nrow * 128 + mcol];
                float4 x2 = *(float4*)&sm[nrow * 128 + mcol + 4];
                x1.x += bz; x1.y += bz; x1.z += bz; x1.w += bz;
                x2.x += bz; x2.y += bz; x2.z += bz; x2.w += bz;
                float* op = out + ((size_t)win * 360 + n) * 128 + mcol;
                *(float4*)op = x1;
                *(float4*)(op + 4) = x2;
            }
            __syncthreads();
        }
        return;
    }

    // float2 epilogues
#pragma unroll
    for (int i = 0; i < 4; i++)
#pragma unroll
        for (int rh = 0; rh < 2; rh++) {
            int m = m0 + wm + i * 16 + g + rh * 8;
            size_t drow;
            if (EPI == 2) {
                drow = roll_offset(m >> 7, m & 127);
            } else {
                drow = (size_t)m * Ntot;
            }
#pragma unroll
            for (int j = 0; j < 4; j++) {
                int n = n0 + wn + j * 8 + 2 * th;
                if (n >= Ntot) continue;
                float2 v = make_float2(d[i][j][rh * 2], d[i][j][rh * 2 + 1]);
                if (EPI == 2) {
                    const float* e = extra + drow + n;
                    v.x += bias[n] + e[0];
                    v.y += bias[n + 1] + e[1];
                } else if (EPI == 3) {
                    const float* bp = (n < 240) ? (bias + n) : (bias2 + n - 240);
                    v.x += bp[0];
                    v.y += bp[1];
                } else {  // EPI 4
                    const float* e = extra + (size_t)m * 120 + n;
                    v.x += bias[n] + e[0];
                    v.y += bias[n + 1] + e[1];
                }
                *(float2*)(out + drow + n) = v;
            }
        }
}

// ---------------- K4: attention (self + mutual), block = (window, head) ----
__global__ void __launch_bounds__(128) k_attn(const float* __restrict__ rpb) {
    __shared__ float sk[128 * 24];
    __shared__ float sv[128 * 24];
    __shared__ float srpb[675];
    __shared__ int   sg[128];

    int wi = blockIdx.x, h = blockIdx.y;
    int t = threadIdx.x;

    for (int i = t; i < 675; i += 128) srpb[i] = rpb[i * 6 + h];

    // token / window coordinates
    int dt = t >> 6, ht = (t >> 3) & 7, wt = t & 7;
    int dB = (wi >> 6) & 3, hB = (wi >> 3) & 7, wB = wi & 7;
    int dd = dB * 2 + dt, hh = hB * 8 + ht, ww = wB * 8 + wt;
    int gd = (dd < 6) ? 0 : ((dd < 7) ? 1 : 2);
    int gh = (hh < 56) ? 0 : ((hh < 60) ? 1 : 2);
    int gw = (ww < 56) ? 0 : ((ww < 60) ? 1 : 2);
    int grp = gd * 9 + gh * 3 + gw;
    int gd0 = (dB * 2 < 6) ? 0 : 1;
    int grp0 = gd0 * 9 + gh * 3 + gw;
    int ccode = dt * 225 + ht * 15 + wt;
    sg[t] = ccode | (grp << 10) | (grp0 << 16);
    int rbase = (dt + 1) * 225 + (ht + 7) * 15 + (wt + 7);

    // ---- self QKV load (coalesced) ----
    const float* Q = g_qkv_s + (size_t)wi * 360 * 128;
    ull q2[10];
#pragma unroll
    for (int d = 0; d < 10; d++) {
        float lo = Q[(h * 20 + 2 * d) * 128 + t] * SCALE_F;
        float hi = Q[(h * 20 + 2 * d + 1) * 128 + t] * SCALE_F;
        q2[d] = pack2(lo, hi);
    }
#pragma unroll
    for (int d = 0; d < 20; d++) {
        sk[t * 24 + d] = Q[(120 + h * 20 + d) * 128 + t];
        sv[t * 24 + d] = Q[(240 + h * 20 + d) * 128 + t];
    }
    __syncthreads();

    ull o2[10];
#pragma unroll
    for (int d = 0; d < 10; d++) o2[d] = 0ULL;
    float sum = 0.f;

#pragma unroll 2
    for (int m = 0; m < 128; m++) {
        int s = sg[m];
        const ulonglong2* kr = (const ulonglong2*)(sk + m * 24);
        ulonglong2 k0 = kr[0], k1 = kr[1], k2 = kr[2], k3 = kr[3], k4 = kr[4];
        ull aA = 0ULL, aB = 0ULL;
        fma2(aA, q2[0], k0.x); fma2(aB, q2[1], k0.y);
        fma2(aA, q2[2], k1.x); fma2(aB, q2[3], k1.y);
        fma2(aA, q2[4], k2.x); fma2(aB, q2[5], k2.y);
        fma2(aA, q2[6], k3.x); fma2(aB, q2[7], k3.y);
        fma2(aA, q2[8], k4.x); fma2(aB, q2[9], k4.y);
        float2 fa = u2f(aA), fb = u2f(aB);
        float logit = (fa.x + fa.y) + (fb.x + fb.y) + srpb[rbase - (s & 1023)];
        float p = (((s >> 10) & 31) == grp) ? __expf(logit) : 0.f;
        sum += p;
        ull pd = pack2(p, p);
        const ulonglong2* vr = (const ulonglong2*)(sv + m * 24);
        ulonglong2 v0 = vr[0], v1 = vr[1], v2 = vr[2], v3 = vr[3], v4 = vr[4];
        fma2(o2[0], pd, v0.x); fma2(o2[1], pd, v0.y);
        fma2(o2[2], pd, v1.x); fma2(o2[3], pd, v1.y);
        fma2(o2[4], pd, v2.x); fma2(o2[5], pd, v2.y);
        fma2(o2[6], pd, v3.x); fma2(o2[7], pd, v3.y);
        fma2(o2[8], pd, v4.x); fma2(o2[9], pd, v4.y);
    }
    {
        float inv = 1.0f / sum;
        float* ob = g_xout + ((size_t)wi * 240 + 120 + h * 20) * 128 + t;
#pragma unroll
        for (int d = 0; d < 10; d++) {
            float2 f = u2f(o2[d]);
            ob[(2 * d) * 128]     = f2tf32(f.x * inv);
            ob[(2 * d + 1) * 128] = f2tf32(f.y * inv);
        }
    }
    __syncthreads();  // done with sk/sv before overwrite

    // ---- mutual attention ----
    int qrow = t ^ 64;
    int mb   = (t < 64) ? 0 : 64;
    const float* Qm = g_qkv_m + (size_t)wi * 360 * 128;
#pragma unroll
    for (int d = 0; d < 20; d++) {
        sk[t * 24 + d] = Qm[(120 + h * 20 + d) * 128 + t];
        sv[t * 24 + d] = Qm[(240 + h * 20 + d) * 128 + t];
    }
    ull q2b[10];
#pragma unroll
    for (int d = 0; d < 10; d++) {
        float lo = Qm[(h * 20 + 2 * d) * 128 + qrow] * SCALE_F;
        float hi = Qm[(h * 20 + 2 * d + 1) * 128 + qrow] * SCALE_F;
        q2b[d] = pack2(lo, hi);
    }
    __syncthreads();

#pragma unroll
    for (int d = 0; d < 10; d++) o2[d] = 0ULL;
    sum = 0.f;
    int mygrp0 = (sg[t & 63] >> 16) & 31;

#pragma unroll 2
    for (int m = 0; m < 64; m++) {
        int s = sg[m];
        const ulonglong2* kr = (const ulonglong2*)(sk + (mb + m) * 24);
        ulonglong2 k0 = kr[0], k1 = kr[1], k2 = kr[2], k3 = kr[3], k4 = kr[4];
        ull aA = 0ULL, aB = 0ULL;
        fma2(aA, q2b[0], k0.x); fma2(aB, q2b[1], k0.y);
        fma2(aA, q2b[2], k1.x); fma2(aB, q2b[3], k1.y);
        fma2(aA, q2b[4], k2.x); fma2(aB, q2b[5], k2.y);
        fma2(aA, q2b[6], k3.x); fma2(aB, q2b[7], k3.y);
        fma2(aA, q2b[8], k4.x); fma2(aB, q2b[9], k4.y);
        float2 fa = u2f(aA), fb = u2f(aB);
        float logit = (fa.x + fa.y) + (fb.x + fb.y);
        float p = (((s >> 16) & 31) == mygrp0) ? __expf(logit) : 0.f;
        sum += p;
        ull pd = pack2(p, p);
        const ulonglong2* vr = (const ulonglong2*)(sv + (mb + m) * 24);
        ulonglong2 v0 = vr[0], v1 = vr[1], v2 = vr[2], v3 = vr[3], v4 = vr[4];
        fma2(o2[0], pd, v0.x); fma2(o2[1], pd, v0.y);
        fma2(o2[2], pd, v1.x); fma2(o2[3], pd, v1.y);
        fma2(o2[4], pd, v2.x); fma2(o2[5], pd, v2.y);
        fma2(o2[6], pd, v3.x); fma2(o2[7], pd, v3.y);
        fma2(o2[8], pd, v4.x); fma2(o2[9], pd, v4.y);
    }
    {
        float inv = 1.0f / sum;
        float* ob = g_xout + ((size_t)wi * 240 + h * 20) * 128 + t;
#pragma unroll
        for (int d = 0; d < 10; d++) {
            float2 f = u2f(o2[d]);
            ob[(2 * d) * 128]     = f2tf32(f.x * inv);
            ob[(2 * d + 1) * 128] = f2tf32(f.y * inv);
        }
    }
}

// ---------------- launch ----------------
extern "C" void kernel_launch(void* const* d_in, const int* in_sizes, int n_in,
                              void* d_out, int out_size) {
    const float* x          = (const float*)d_in[0];
    const float* g1         = (const float*)d_in[2];
    const float* b1         = (const float*)d_in[3];
    const float* qkv_self_w = (const float*)d_in[4];
    const float* qkv_self_b = (const float*)d_in[5];
    const float* qkv_mut_w  = (const float*)d_in[6];
    const float* qkv_mut_b  = (const float*)d_in[7];
    const float* proj_w     = (const float*)d_in[8];
    const float* proj_b     = (const float*)d_in[9];
    const float* rpb        = (const float*)d_in[10];
    const float* pos        = (const float*)d_in[11];
    const float* g2         = (const float*)d_in[12];
    const float* b2         = (const float*)d_in[13];
    const float* fc11_w     = (const float*)d_in[14];
    const float* fc11_b     = (const float*)d_in[15];
    const float* fc12_w     = (const float*)d_in[16];
    const float* fc12_b     = (const float*)d_in[17];
    const float* fc2_w      = (const float*)d_in[18];
    const float* fc2_b      = (const float*)d_in[19];
    float* out = (float*)d_out;

    float* xw   = nullptr; cudaGetSymbolAddress((void**)&xw,   g_xw);
    float* xwm  = nullptr; cudaGetSymbolAddress((void**)&xwm,  g_xwm);
    float* qkvs = nullptr; cudaGetSymbolAddress((void**)&qkvs, g_qkv_s);
    float* qkvm = nullptr; cudaGetSymbolAddress((void**)&qkvm, g_qkv_m);
    float* xo   = nullptr; cudaGetSymbolAddress((void**)&xo,   g_xout);
    float* xres = nullptr; cudaGetSymbolAddress((void**)&xres, g_xres);
    float* zb   = nullptr; cudaGetSymbolAddress((void**)&zb,   g_z);
    float* hb   = nullptr; cudaGetSymbolAddress((void**)&hb,   g_h);
    float* actb = nullptr; cudaGetSymbolAddress((void**)&actb, g_act);
    float* wts  = nullptr; cudaGetSymbolAddress((void**)&wts,  g_wts);

    // 0. round weights to tf32
    k_wcvt<<<(64800 + 255) / 256, 256>>>(qkv_self_w, qkv_mut_w, proj_w,
                                         fc11_w, fc12_w, fc2_w);
    // 1. LN1 + roll + window partition (+ pos-biased copy)
    k_ln1<<<NTOK / 8, 256>>>(x, g1, b1, pos);
    // 2. QKV self (-> [win][360][128])
    k_gemm<120, 0, 1, 0><<<dim3(NTOK / 128, 3), 256>>>(
        xw, wts + W_QS, nullptr, qkv_self_b, nullptr, nullptr, qkvs, 360);
    // 3. QKV mutual (A already pos-biased, -> [win][360][128])
    k_gemm<120, 0, 1, 0><<<dim3(NTOK / 128, 3), 256>>>(
        xwm, wts + W_QM, nullptr, qkv_mut_b, nullptr, nullptr, qkvm, 360);
    // 4. attention (-> g_xout [win][240][128])
    k_attn<<<dim3(NWIN, 6), 128>>>(rpb);
    // 5. proj + window-reverse + roll-back + shortcut add
    k_gemm<240, 2, 0, 2><<<dim3(NTOK / 128, 1), 256>>>(
        xo, wts + W_PR, nullptr, proj_b, nullptr, x, xres, 120);
    // 6. LN2
    k_ln2<<<NTOK / 8, 256>>>(g2, b2);
    // 7. fc11 | fc12 (EPI 3 selects split B source)
    k_gemm<120, 0, 0, 3><<<dim3(NTOK / 128, 4), 256>>>(
        zb, wts + W_F11, wts + W_F12, fc11_b, fc12_b, nullptr, hb, 480);
    // 8. gated gelu elementwise
    k_act<<<(NTOK * 60 + 255) / 256, 256>>>();
    // 9. fc2 + residual -> out
    k_gemm<240, 0, 0, 4><<<dim3(NTOK / 128, 1), 256>>>(
        actb, wts + W_F2, nullptr, fc2_b, nullptr, xres, out, 120);
}